// round 17
// baseline (speedup 1.0000x reference)
#include <cuda_runtime.h>
#include <cuda_bf16.h>
#include <math.h>
#include <stdint.h>

#define Bdim 16
#define Ldim 4096
#define Cdim 256
#define Ddim 512
#define EPSF 1e-8f

typedef unsigned long long ull;

// ------------------- scratch (device globals; no allocs allowed) -------------------
__device__ float g_attn[(size_t)Bdim * 4 * Ldim];           // [b][i][l]
__device__ __nv_bfloat16 gF_hi[(size_t)Bdim * Ldim * 512];  // feats (post-gelu) [b][l][512]
__device__ __nv_bfloat16 gF_lo[(size_t)Bdim * Ldim * 512];
__device__ __nv_bfloat16 gB_hi[512 * 768];                  // [o][768]: fw | rw
__device__ __nv_bfloat16 gB_lo[512 * 768];
__device__ __nv_bfloat16 pwB_hi[4 * 128 * 256];             // [sc][o][c]
__device__ __nv_bfloat16 pwB_lo[4 * 128 * 256];
__device__ __nv_bfloat16 w1B_hi[128 * 512];                 // [dh][d]
__device__ __nv_bfloat16 w1B_lo[128 * 512];

// ------------------- helpers -------------------
__device__ __forceinline__ void cpa16(void* dst, const void* src) {
    unsigned s = (unsigned)__cvta_generic_to_shared(dst);
    asm volatile("cp.async.cg.shared.global [%0], [%1], 16;" :: "r"(s), "l"(src));
}
#define CP_COMMIT() asm volatile("cp.async.commit_group;")
#define CP_WAIT0()  asm volatile("cp.async.wait_group 0;" ::: "memory")

__device__ __forceinline__ uint32_t smem_u32(const void* p) {
    uint32_t a;
    asm("{ .reg .u64 t; cvta.to.shared.u64 t, %1; cvt.u32.u64 %0, t; }" : "=r"(a) : "l"(p));
    return a;
}
__device__ __forceinline__ void ldm_x4(uint32_t r[4], uint32_t addr) {
    asm volatile("ldmatrix.sync.aligned.m8n8.x4.shared.b16 {%0,%1,%2,%3}, [%4];"
                 : "=r"(r[0]), "=r"(r[1]), "=r"(r[2]), "=r"(r[3]) : "r"(addr));
}
__device__ __forceinline__ void mma_bf16(float c[4], const uint32_t a[4],
                                         uint32_t b0, uint32_t b1) {
    asm volatile("mma.sync.aligned.m16n8k16.row.col.f32.bf16.bf16.f32 "
                 "{%0,%1,%2,%3}, {%4,%5,%6,%7}, {%8,%9}, {%0,%1,%2,%3};"
                 : "+f"(c[0]), "+f"(c[1]), "+f"(c[2]), "+f"(c[3])
                 : "r"(a[0]), "r"(a[1]), "r"(a[2]), "r"(a[3]), "r"(b0), "r"(b1));
}
__device__ __forceinline__ void split_bf16(float v, __nv_bfloat16& hi, __nv_bfloat16& lo) {
    hi = __float2bfloat16(v);
    lo = __float2bfloat16(v - __bfloat162float(hi));
}
__device__ __forceinline__ uint32_t pack_bf2(__nv_bfloat16 a, __nv_bfloat16 b) {
    uint16_t ua = *(uint16_t*)&a, ub = *(uint16_t*)&b;
    return (uint32_t)ua | ((uint32_t)ub << 16);
}

// ------------------- K0: split all tensor-path weights to bf16 hi/lo -------------------
__global__ void k_prepW(const float* __restrict__ pw1, const float* __restrict__ pw3,
                        const float* __restrict__ pw5, const float* __restrict__ pw7,
                        const float* __restrict__ w1,
                        const float* __restrict__ fw, const float* __restrict__ rw) {
    int idx = blockIdx.x * blockDim.x + threadIdx.x;
    if (idx >= 589824) return;
    float v;
    __nv_bfloat16 hi, lo;
    if (idx < 131072) {
        int s = idx >> 15, r = idx & 32767;
        int o = r >> 8, c = r & 255;
        const float* pw = (s == 0) ? pw1 : (s == 1) ? pw3 : (s == 2) ? pw5 : pw7;
        v = pw[o * 256 + c];
        split_bf16(v, hi, lo);
        pwB_hi[idx] = hi; pwB_lo[idx] = lo;
    } else if (idx < 196608) {
        int r = idx - 131072;
        v = w1[r];
        split_bf16(v, hi, lo);
        w1B_hi[r] = hi; w1B_lo[r] = lo;
    } else {
        int r = idx - 196608;
        int o = r / 768, d = r % 768;
        v = (d < 512) ? fw[o * 512 + d] : rw[o * 256 + (d - 512)];
        split_bf16(v, hi, lo);
        gB_hi[r] = hi; gB_lo[r] = lo;
    }
}

// ------------------- K1: conv (scalar) + pointwise (mma bf16x3) + RMSNorm + GELU -------------------
#define KC_XS  0
#define KC_AH  17152
#define KC_AL  27392
#define KC_PW0 37632
#define KC_PW1 58112
#define KC_SM  78592
__global__ __launch_bounds__(256, 2) void k_conv(
    const float* __restrict__ x,
    const float* __restrict__ dw1, const float* __restrict__ dw3,
    const float* __restrict__ dw5, const float* __restrict__ dw7,
    const float* __restrict__ cn1, const float* __restrict__ cn3,
    const float* __restrict__ cn5, const float* __restrict__ cn7) {
    extern __shared__ char smc[];
    float* xs = (float*)(smc + KC_XS);

    int tid = threadIdx.x, lane = tid & 31, warp = tid >> 5;
    int wm = warp >> 1, wn = warp & 1;
    int lt = blockIdx.x, b = blockIdx.y, sc = blockIdx.z;
    int l0 = lt * 128;
    int k = 2 * sc + 1, r = sc;
    bool edge = (lt == 0) || (lt == Ldim / 128 - 1);
    const float* dw = (sc == 0) ? dw1 : (sc == 1) ? dw3 : (sc == 2) ? dw5 : dw7;
    const float* cn = (sc == 0) ? cn1 : (sc == 1) ? cn3 : (sc == 2) ? cn5 : cn7;
    const __nv_bfloat16* pwh = pwB_hi + sc * 32768;
    const __nv_bfloat16* pwl = pwB_lo + sc * 32768;
    uint32_t sb = smem_u32(smc);

    int c2 = (tid & 15) << 1;
    int lgrp = tid >> 4;

    float c[2][8][4];
    #pragma unroll
    for (int t = 0; t < 2; t++)
        #pragma unroll
        for (int n = 0; n < 8; n++)
            #pragma unroll
            for (int q = 0; q < 4; q++) c[t][n][q] = 0.f;

    auto stage_x = [&](int c0) {
        if (!edge) {
            for (int u = tid; u < 1072; u += 256) {
                int i = u >> 3, seg = u & 7;
                cpa16(smc + KC_XS + i * 128 + seg * 16,
                      x + ((size_t)b * Ldim + l0 - 3 + i) * Cdim + c0 + seg * 4);
            }
        } else {
            for (int u = tid; u < 4288; u += 256) {
                int i = u >> 5, cc = u & 31;
                int gl = l0 - 3 + i;
                xs[u] = (gl >= 0 && gl < Ldim)
                      ? x[((size_t)b * Ldim + gl) * Cdim + c0 + cc] : 0.f;
            }
        }
    };
    auto stage_pw = [&](int c0, int buf) {
        char* base = smc + (buf ? KC_PW1 : KC_PW0);
        for (int u = tid; u < 512; u += 256) {
            int o = u >> 2, seg = u & 3;
            cpa16(base + o * 80 + seg * 16, pwh + (size_t)o * 256 + c0 + seg * 8);
            cpa16(base + 10240 + o * 80 + seg * 16, pwl + (size_t)o * 256 + c0 + seg * 8);
        }
    };

    stage_x(0);
    stage_pw(0, 0);
    CP_COMMIT();

    for (int ci = 0; ci < 8; ci++) {
        int c0 = ci * 32;
        CP_WAIT0();
        __syncthreads();
        float rd0[7], rd1[7];
        #pragma unroll
        for (int t = 0; t < 7; t++) {
            rd0[t] = (t < k) ? dw[(c0 + c2) * k + t] : 0.f;
            rd1[t] = (t < k) ? dw[(c0 + c2 + 1) * k + t] : 0.f;
        }
        #pragma unroll
        for (int ii = 0; ii < 8; ii++) {
            int l = lgrp * 8 + ii;
            float s0 = 0.f, s1 = 0.f;
            for (int t = 0; t < k; t++) {
                float2 xv = *(const float2*)&xs[(l + 3 - r + t) * 32 + c2];
                s0 += rd0[t] * xv.x;
                s1 += rd1[t] * xv.y;
            }
            __nv_bfloat16 h0, lo0, h1, lo1;
            split_bf16(s0, h0, lo0);
            split_bf16(s1, h1, lo1);
            *(uint32_t*)(smc + KC_AH + l * 80 + c2 * 2) = pack_bf2(h0, h1);
            *(uint32_t*)(smc + KC_AL + l * 80 + c2 * 2) = pack_bf2(lo0, lo1);
        }
        __syncthreads();
        if (ci < 7) {
            stage_x(c0 + 32);
            stage_pw(c0 + 32, (ci + 1) & 1);
            CP_COMMIT();
        }
        uint32_t pwbuf = sb + ((ci & 1) ? KC_PW1 : KC_PW0);
        int quad = lane >> 3, rr = lane & 7;
        #pragma unroll
        for (int s = 0; s < 2; s++) {
            int k0 = s * 16;
            uint32_t ah[2][4], al[2][4];
            #pragma unroll
            for (int t = 0; t < 2; t++) {
                int row = wm * 32 + t * 16 + (lane & 15);
                uint32_t ad = sb + KC_AH + row * 80 + (k0 + ((lane >> 4) << 3)) * 2;
                ldm_x4(ah[t], ad);
                ldm_x4(al[t], ad + (KC_AL - KC_AH));
            }
            uint32_t bh[4][4], bl[4][4];
            #pragma unroll
            for (int p = 0; p < 4; p++) {
                int n = wn * 64 + p * 16 + ((quad >> 1) << 3) + rr;
                uint32_t bd = pwbuf + n * 80 + (k0 + ((quad & 1) << 3)) * 2;
                ldm_x4(bh[p], bd);
                ldm_x4(bl[p], bd + 10240);
            }
            #pragma unroll
            for (int t = 0; t < 2; t++)
                #pragma unroll
                for (int nt = 0; nt < 8; nt++) {
                    int p = nt >> 1, w2 = (nt & 1) * 2;
                    mma_bf16(c[t][nt], ah[t], bh[p][w2], bh[p][w2 + 1]);
                    mma_bf16(c[t][nt], ah[t], bl[p][w2], bl[p][w2 + 1]);
                    mma_bf16(c[t][nt], al[t], bh[p][w2], bh[p][w2 + 1]);
                }
        }
    }
    __syncthreads();

    float* red = (float*)(smc + KC_XS);   // [128][2]
    int gid = lane >> 2, tig = lane & 3;
    #pragma unroll
    for (int t = 0; t < 2; t++) {
        float p0 = 0.f, p1 = 0.f;
        #pragma unroll
        for (int nt = 0; nt < 8; nt++) {
            p0 += c[t][nt][0] * c[t][nt][0] + c[t][nt][1] * c[t][nt][1];
            p1 += c[t][nt][2] * c[t][nt][2] + c[t][nt][3] * c[t][nt][3];
        }
        p0 += __shfl_xor_sync(0xFFFFFFFFu, p0, 1);
        p0 += __shfl_xor_sync(0xFFFFFFFFu, p0, 2);
        p1 += __shfl_xor_sync(0xFFFFFFFFu, p1, 1);
        p1 += __shfl_xor_sync(0xFFFFFFFFu, p1, 2);
        if (tig == 0) {
            int r0 = wm * 32 + t * 16 + gid;
            red[r0 * 2 + wn] = p0;
            red[(r0 + 8) * 2 + wn] = p1;
        }
    }
    __syncthreads();
    #pragma unroll
    for (int t = 0; t < 2; t++) {
        int r0 = wm * 32 + t * 16 + gid;
        float inv0 = 1.f / (sqrtf((red[r0 * 2] + red[r0 * 2 + 1]) * (1.f / 128.f)) + EPSF);
        float inv1 = 1.f / (sqrtf((red[(r0 + 8) * 2] + red[(r0 + 8) * 2 + 1]) * (1.f / 128.f)) + EPSF);
        #pragma unroll
        for (int nt = 0; nt < 8; nt++) {
            int o = wn * 64 + nt * 8 + tig * 2;
            float cn0 = cn[o], cn1 = cn[o + 1];
            float h00 = c[t][nt][0] * cn0 * inv0, h01 = c[t][nt][1] * cn1 * inv0;
            float h10 = c[t][nt][2] * cn0 * inv1, h11 = c[t][nt][3] * cn1 * inv1;
            h00 *= normcdff(h00); h01 *= normcdff(h01);
            h10 *= normcdff(h10); h11 *= normcdff(h11);
            size_t row0 = ((size_t)b * Ldim + l0 + r0) * 512 + sc * 128 + o;
            size_t row1 = row0 + 8 * 512;
            __nv_bfloat16 a0h, a0l, a1h, a1l;
            split_bf16(h00, a0h, a0l); split_bf16(h01, a1h, a1l);
            *(uint32_t*)(gF_hi + row0) = pack_bf2(a0h, a1h);
            *(uint32_t*)(gF_lo + row0) = pack_bf2(a0l, a1l);
            split_bf16(h10, a0h, a0l); split_bf16(h11, a1h, a1l);
            *(uint32_t*)(gF_hi + row1) = pack_bf2(a0h, a1h);
            *(uint32_t*)(gF_lo + row1) = pack_bf2(a0l, a1l);
        }
    }
}

// ------------------- K2: attention MLP (mma bf16x3) + softmax -------------------
#define KA_A0  0
#define KA_A1  20480
#define KA_B0  40960
#define KA_B1  61440
#define KA_W2  81920
#define KA_SM  83968
__global__ __launch_bounds__(256, 2) void k_attn(const float* __restrict__ b1p,
                                                 const float* __restrict__ w2p,
                                                 const float* __restrict__ b2p) {
    extern __shared__ char smc[];
    float* w2s = (float*)(smc + KA_W2);
    int tid = threadIdx.x, lane = tid & 31, warp = tid >> 5;
    int wm = warp >> 1, wn = warp & 1;
    int b = blockIdx.y;
    int l0 = blockIdx.x * 128;
    uint32_t sb = smem_u32(smc);
    size_t bL = (size_t)b * Ldim + l0;

    w2s[tid] = w2p[tid];
    w2s[tid + 256] = w2p[tid + 256];

    float c[2][8][4];
    #pragma unroll
    for (int t = 0; t < 2; t++)
        #pragma unroll
        for (int n = 0; n < 8; n++)
            #pragma unroll
            for (int q = 0; q < 4; q++) c[t][n][q] = 0.f;

    auto stage = [&](int c0, int buf) {
        char* ab = smc + (buf ? KA_A1 : KA_A0);
        char* bb = smc + (buf ? KA_B1 : KA_B0);
        for (int u = tid; u < 512; u += 256) {
            int row = u >> 2, seg = u & 3;
            size_t ao = (bL + row) * 512 + c0 + seg * 8;
            cpa16(ab + row * 80 + seg * 16, gF_hi + ao);
            cpa16(ab + 10240 + row * 80 + seg * 16, gF_lo + ao);
            size_t bo = (size_t)row * 512 + c0 + seg * 8;
            cpa16(bb + row * 80 + seg * 16, w1B_hi + bo);
            cpa16(bb + 10240 + row * 80 + seg * 16, w1B_lo + bo);
        }
    };

    stage(0, 0);
    CP_COMMIT();

    for (int ci = 0; ci < 16; ci++) {
        CP_WAIT0();
        __syncthreads();
        if (ci < 15) {
            stage((ci + 1) * 32, (ci + 1) & 1);
            CP_COMMIT();
        }
        uint32_t abuf = sb + ((ci & 1) ? KA_A1 : KA_A0);
        uint32_t bbuf = sb + ((ci & 1) ? KA_B1 : KA_B0);
        int quad = lane >> 3, rr = lane & 7;
        #pragma unroll
        for (int s = 0; s < 2; s++) {
            int k0 = s * 16;
            uint32_t ah[2][4], al[2][4];
            #pragma unroll
            for (int t = 0; t < 2; t++) {
                int row = wm * 32 + t * 16 + (lane & 15);
                uint32_t ad = abuf + row * 80 + (k0 + ((lane >> 4) << 3)) * 2;
                ldm_x4(ah[t], ad);
                ldm_x4(al[t], ad + 10240);
            }
            uint32_t bh[4][4], bl[4][4];
            #pragma unroll
            for (int p = 0; p < 4; p++) {
                int n = wn * 64 + p * 16 + ((quad >> 1) << 3) + rr;
                uint32_t bd = bbuf + n * 80 + (k0 + ((quad & 1) << 3)) * 2;
                ldm_x4(bh[p], bd);
                ldm_x4(bl[p], bd + 10240);
            }
            #pragma unroll
            for (int t = 0; t < 2; t++)
                #pragma unroll
                for (int nt = 0; nt < 8; nt++) {
                    int p = nt >> 1, w2 = (nt & 1) * 2;
                    mma_bf16(c[t][nt], ah[t], bh[p][w2], bh[p][w2 + 1]);
                    mma_bf16(c[t][nt], ah[t], bl[p][w2], bl[p][w2 + 1]);
                    mma_bf16(c[t][nt], al[t], bh[p][w2], bh[p][w2 + 1]);
                }
        }
    }
    __syncthreads();

    float* red4 = (float*)smc;
    int gid = lane >> 2, tig = lane & 3;
    float part[4][2][2];
    #pragma unroll
    for (int i4 = 0; i4 < 4; i4++)
        #pragma unroll
        for (int t = 0; t < 2; t++) { part[i4][t][0] = 0.f; part[i4][t][1] = 0.f; }
    #pragma unroll
    for (int t = 0; t < 2; t++)
        #pragma unroll
        for (int nt = 0; nt < 8; nt++) {
            int dh = wn * 64 + nt * 8 + tig * 2;
            float b10 = b1p[dh], b11 = b1p[dh + 1];
            float g00 = c[t][nt][0] + b10, g01 = c[t][nt][1] + b11;
            float g10 = c[t][nt][2] + b10, g11 = c[t][nt][3] + b11;
            g00 *= normcdff(g00); g01 *= normcdff(g01);
            g10 *= normcdff(g10); g11 *= normcdff(g11);
            #pragma unroll
            for (int i4 = 0; i4 < 4; i4++) {
                float w0 = w2s[i4 * 128 + dh], w1v = w2s[i4 * 128 + dh + 1];
                part[i4][t][0] += w0 * g00 + w1v * g01;
                part[i4][t][1] += w0 * g10 + w1v * g11;
            }
        }
    #pragma unroll
    for (int i4 = 0; i4 < 4; i4++)
        #pragma unroll
        for (int t = 0; t < 2; t++)
            #pragma unroll
            for (int rr2 = 0; rr2 < 2; rr2++) {
                float p = part[i4][t][rr2];
                p += __shfl_xor_sync(0xFFFFFFFFu, p, 1);
                p += __shfl_xor_sync(0xFFFFFFFFu, p, 2);
                part[i4][t][rr2] = p;
            }
    if (tig == 0) {
        #pragma unroll
        for (int i4 = 0; i4 < 4; i4++)
            #pragma unroll
            for (int t = 0; t < 2; t++) {
                int r0 = wm * 32 + t * 16 + gid;
                red4[(i4 * 128 + r0) * 2 + wn] = part[i4][t][0];
                red4[(i4 * 128 + r0 + 8) * 2 + wn] = part[i4][t][1];
            }
    }
    __syncthreads();
    if (wn == 0 && tig == 0) {
        #pragma unroll
        for (int t = 0; t < 2; t++)
            #pragma unroll
            for (int rr2 = 0; rr2 < 2; rr2++) {
                int l = wm * 32 + t * 16 + gid + rr2 * 8;
                float a2[4];
                #pragma unroll
                for (int i4 = 0; i4 < 4; i4++)
                    a2[i4] = red4[(i4 * 128 + l) * 2] + red4[(i4 * 128 + l) * 2 + 1] + b2p[i4];
                float m = fmaxf(fmaxf(a2[0], a2[1]), fmaxf(a2[2], a2[3]));
                float s = 0.f;
                #pragma unroll
                for (int i4 = 0; i4 < 4; i4++) { a2[i4] = expf(a2[i4] - m); s += a2[i4]; }
                float invs = 1.f / s;
                #pragma unroll
                for (int i4 = 0; i4 < 4; i4++)
                    g_attn[((size_t)b * 4 + i4) * Ldim + l0 + l] = a2[i4] * invs;
            }
    }
}

// ------------------- K3: fused final GEMM, 512 threads, warp tile 32x32 -------------------
#define KF_A0 0
#define KF_A1 20480
#define KF_B0 40960
#define KF_B1 61440
#define KF_AT 81920
#define KF_SM 83968
__global__ __launch_bounds__(512, 2) void k_final_mma(const float* __restrict__ x,
                                                      float* __restrict__ out) {
    extern __shared__ char smc[];
    float* atts = (float*)(smc + KF_AT);
    int tid = threadIdx.x, lane = tid & 31, warp = tid >> 5;
    int wm = warp >> 2, wn = warp & 3;       // 4x4 warp grid, 32x32 tiles
    int ot = blockIdx.x, lt = blockIdx.y, b = blockIdx.z;
    int l0 = lt * 128, o0 = ot * 128;
    uint32_t sb = smem_u32(smc);

    atts[tid] = g_attn[((size_t)b * 4 + (tid >> 7)) * Ldim + l0 + (tid & 127)];

    int arow = tid >> 2, aseg = tid & 3;     // 128 rows x 4 segs of 8 cols
    size_t xrow = (size_t)b * Ldim + l0 + arow;
    const __nv_bfloat16* Bhg = gB_hi + (size_t)o0 * 768;
    const __nv_bfloat16* Blg = gB_lo + (size_t)o0 * 768;

    float c[2][4][4];
    #pragma unroll
    for (int t = 0; t < 2; t++)
        #pragma unroll
        for (int n = 0; n < 4; n++)
            #pragma unroll
            for (int q = 0; q < 4; q++) c[t][n][q] = 0.f;

    uint4 r0, r1;
    auto prefetch = [&](int c0) {
        if (c0 < 512) {
            size_t base = xrow * 512 + c0 + aseg * 8;
            r0 = *(const uint4*)(gF_hi + base);
            r1 = *(const uint4*)(gF_lo + base);
        } else {
            size_t base = xrow * 256 + (c0 - 512) + aseg * 8;
            r0 = *(const uint4*)(x + base);
            r1 = *(const uint4*)(x + base + 4);
        }
    };
    auto sts_a = [&](int c0, int buf) {
        char* ab = smc + (buf ? KF_A1 : KF_A0);
        float f[8];
        uint4 rr4[2] = {r0, r1};
        if (c0 < 512) {
            float av = atts[((c0 >> 7) << 7) + arow];
            const __nv_bfloat16* ph = (const __nv_bfloat16*)&rr4[0];
            const __nv_bfloat16* pl = (const __nv_bfloat16*)&rr4[1];
            #pragma unroll
            for (int e = 0; e < 8; e++)
                f[e] = (__bfloat162float(ph[e]) + __bfloat162float(pl[e])) * av;
        } else {
            const float* pf = (const float*)rr4;
            #pragma unroll
            for (int e = 0; e < 8; e++) f[e] = pf[e];
        }
        uint32_t oh[4], ol[4];
        #pragma unroll
        for (int e2 = 0; e2 < 4; e2++) {
            __nv_bfloat16 h0, lo0, h1, lo1;
            split_bf16(f[2 * e2], h0, lo0);
            split_bf16(f[2 * e2 + 1], h1, lo1);
            oh[e2] = pack_bf2(h0, h1);
            ol[e2] = pack_bf2(lo0, lo1);
        }
        char* dh = ab + arow * 80 + aseg * 16;
        *(uint4*)dh = make_uint4(oh[0], oh[1], oh[2], oh[3]);
        *(uint4*)(dh + 10240) = make_uint4(ol[0], ol[1], ol[2], ol[3]);
    };
    auto stage_b = [&](int c0, int buf) {
        char* bb = smc + (buf ? KF_B1 : KF_B0);
        {
            int row = tid >> 2, seg = tid & 3;
            size_t bo = (size_t)row * 768 + c0 + seg * 8;
            cpa16(bb + row * 80 + seg * 16, Bhg + bo);
            cpa16(bb + 10240 + row * 80 + seg * 16, Blg + bo);
        }
    };

    prefetch(0);
    stage_b(0, 0);
    CP_COMMIT();
    __syncthreads();     // atts visible
    sts_a(0, 0);
    prefetch(32);

    for (int ci = 0; ci < 24; ci++) {
        CP_WAIT0();
        __syncthreads();     // publishes A[ci] + B[ci]
        if (ci < 23) {
            stage_b((ci + 1) * 32, (ci + 1) & 1);
            CP_COMMIT();
        }
        uint32_t abuf = sb + ((ci & 1) ? KF_A1 : KF_A0);
        uint32_t bbuf = sb + ((ci & 1) ? KF_B1 : KF_B0);
        int quad = lane >> 3, rrl = lane & 7;
        #pragma unroll
        for (int s = 0; s < 2; s++) {
            int k0 = s * 16;
            uint32_t ah[2][4], al[2][4];
            #pragma unroll
            for (int t = 0; t < 2; t++) {
                int row = wm * 32 + t * 16 + (lane & 15);
                uint32_t ad = abuf + row * 80 + (k0 + ((lane >> 4) << 3)) * 2;
                ldm_x4(ah[t], ad);
                ldm_x4(al[t], ad + 10240);
            }
            #pragma unroll
            for (int p = 0; p < 2; p++) {
                int n = wn * 32 + p * 16 + ((quad >> 1) << 3) + rrl;
                uint32_t bd = bbuf + n * 80 + (k0 + ((quad & 1) << 3)) * 2;
                uint32_t bh4[4], bl4[4];
                ldm_x4(bh4, bd);
                ldm_x4(bl4, bd + 10240);
                #pragma unroll
                for (int half = 0; half < 2; half++) {
                    int nt = 2 * p + half, w2 = half * 2;
                    #pragma unroll
                    for (int t = 0; t < 2; t++) {
                        mma_bf16(c[t][nt], ah[t], bh4[w2], bh4[w2 + 1]);
                        mma_bf16(c[t][nt], ah[t], bl4[w2], bl4[w2 + 1]);
                        mma_bf16(c[t][nt], al[t], bh4[w2], bh4[w2 + 1]);
                    }
                }
            }
        }
        if (ci < 23) sts_a((ci + 1) * 32, (ci + 1) & 1);
        if (ci < 22) prefetch((ci + 2) * 32);
    }

    int gid = lane >> 2, tig = lane & 3;
    #pragma unroll
    for (int t = 0; t < 2; t++) {
        size_t rb = (size_t)b * Ldim + l0 + wm * 32 + t * 16 + gid;
        #pragma unroll
        for (int nt = 0; nt < 4; nt++) {
            int o = o0 + wn * 32 + nt * 8 + tig * 2;
            *(float2*)(out + rb * Ddim + o)       = make_float2(c[t][nt][0], c[t][nt][1]);
            *(float2*)(out + (rb + 8) * Ddim + o) = make_float2(c[t][nt][2], c[t][nt][3]);
        }
    }
}

// ------------------- K4: final row RMSNorm (in place) -------------------
__global__ __launch_bounds__(256) void k_norm(float* __restrict__ out,
                                              const float* __restrict__ nsc) {
    __shared__ float ns[512];
    int tid = threadIdx.x;
    ns[tid] = nsc[tid];
    ns[tid + 256] = nsc[tid + 256];
    __syncthreads();

    int warp = tid >> 5, lane = tid & 31;
    size_t row = (size_t)blockIdx.x * 8 + warp;
    float* p = out + row * Ddim;

    float4 v[4];
    float ssq = 0.f;
    #pragma unroll
    for (int q = 0; q < 4; q++) {
        v[q] = *(const float4*)(p + (q * 32 + lane) * 4);
        ssq += v[q].x * v[q].x + v[q].y * v[q].y + v[q].z * v[q].z + v[q].w * v[q].w;
    }
    #pragma unroll
    for (int off = 16; off > 0; off >>= 1)
        ssq += __shfl_xor_sync(0xFFFFFFFFu, ssq, off);
    float rms = sqrtf(ssq * (1.f / 512.f));
    float inv = 1.f / (rms + EPSF);
    #pragma unroll
    for (int q = 0; q < 4; q++) {
        int base = (q * 32 + lane) * 4;
        float4 w;
        w.x = v[q].x * ns[base + 0] * inv;
        w.y = v[q].y * ns[base + 1] * inv;
        w.z = v[q].z * ns[base + 2] * inv;
        w.w = v[q].w * ns[base + 3] * inv;
        *(float4*)(p + base) = w;
    }
}

// ------------------- launch -------------------
extern "C" void kernel_launch(void* const* d_in, const int* in_sizes, int n_in,
                              void* d_out, int out_size) {
    const float* x = (const float*)d_in[0];
    const float *dw[4], *pw[4], *cnp[4];
    if (in_sizes[2] == 768) {
        for (int i = 0; i < 4; i++) {
            dw[i]  = (const float*)d_in[1 + i];
            pw[i]  = (const float*)d_in[5 + i];
            cnp[i] = (const float*)d_in[9 + i];
        }
    } else {
        for (int i = 0; i < 4; i++) {
            dw[i]  = (const float*)d_in[1 + 3 * i];
            pw[i]  = (const float*)d_in[2 + 3 * i];
            cnp[i] = (const float*)d_in[3 + 3 * i];
        }
    }
    const float* w1  = (const float*)d_in[13];
    const float* b1  = (const float*)d_in[14];
    const float* w2  = (const float*)d_in[15];
    const float* b2  = (const float*)d_in[16];
    const float* fw  = (const float*)d_in[17];
    const float* nsc = (const float*)d_in[18];
    const float* rw  = (const float*)d_in[19];
    float* out = (float*)d_out;

    cudaFuncSetAttribute(k_conv,      cudaFuncAttributeMaxDynamicSharedMemorySize, KC_SM);
    cudaFuncSetAttribute(k_attn,      cudaFuncAttributeMaxDynamicSharedMemorySize, KA_SM);
    cudaFuncSetAttribute(k_final_mma, cudaFuncAttributeMaxDynamicSharedMemorySize, KF_SM);

    k_prepW<<<589824 / 256, 256>>>(pw[0], pw[1], pw[2], pw[3], w1, fw, rw);
    k_conv<<<dim3(Ldim / 128, Bdim, 4), 256, KC_SM>>>(x, dw[0], dw[1], dw[2], dw[3],
                                                      cnp[0], cnp[1], cnp[2], cnp[3]);
    k_attn<<<dim3(Ldim / 128, Bdim), 256, KA_SM>>>(b1, w2, b2);
    k_final_mma<<<dim3(Ddim / 128, Ldim / 128, Bdim), 512, KF_SM>>>(x, out);
    k_norm<<<(Bdim * Ldim) / 8, 256>>>(out, nsc);
}